// round 14
// baseline (speedup 1.0000x reference)
#include <cuda_runtime.h>

#define Bz 32
#define Sz 256
#define Iz 512
#define Hz 256
#define Mz 80
#define Cz 1024
#define C2z 512
#define LOCz 32
#define Kz 31
#define Tz 800
#define XWz (Hz + Iz)         /* 768  */
#define TINz (Iz + Mz + Cz)   /* 1616 */
#define GRID 128
#define NTHR 512

// ---------------- persistent device scratch ----------------
__device__ __align__(16) float g_key[Bz][Sz][C2z];   // immutable after P0
__device__ __align__(16) float g_hT[2][Cz][Bz];      // mutable: P2 -> P1
__device__ __align__(16) float g_hB[2][Bz][Cz];      // mutable: P2 -> P2
__device__ __align__(16) float g_prevT[Iz][Bz];      // mutable: P3 -> P1
__device__ __align__(16) float g_alpha[Bz][Sz];      // same-CTA only (P3)
__device__ __align__(16) float g_align_s[Bz][Sz];    // mutable: P3 -> P2
__device__ __align__(16) float g_gsum[Bz][2 * Cz];   // mutable: P1 -> P2
__device__ __align__(16) float g_gxn[Bz][Cz];        // mutable: P1 -> P2
__device__ __align__(16) float g_ghn[Bz][Cz];        // mutable: P1 -> P2
__device__ __align__(16) float g_wcomb[C2z][Kz];     // immutable after P0
__device__ __align__(16) float g_ep[4][Bz][Sz];      // mutable: P2 -> P3
__device__ __align__(16) float g_zpart[32][Bz];      // mutable: P1 -> P3
__device__ unsigned g_cnt;
__device__ volatile unsigned g_epoch;

// ---------------- helpers ----------------
__device__ __forceinline__ float fsig(float x) {
    return __fdividef(1.f, 1.f + __expf(-x));
}
__device__ __forceinline__ float ftanh(float x) {
    float ax = fabsf(x);
    float e  = __expf(-2.f * ax);
    float r  = __fdividef(1.f - e, 1.f + e);
    return copysignf(r, x);
}
__device__ __forceinline__ float dot4(float4 a, float4 b) {
    return a.x * b.x + a.y * b.y + a.z * b.z + a.w * b.w;
}
__device__ __forceinline__ float4 f4fma(float s, float4 v, float4 a) {
    a.x = fmaf(s, v.x, a.x);
    a.y = fmaf(s, v.y, a.y);
    a.z = fmaf(s, v.z, a.z);
    a.w = fmaf(s, v.w, a.w);
    return a;
}
__device__ __forceinline__ float4 f4add(float4 a, float4 b) {
    a.x += b.x; a.y += b.y; a.z += b.z; a.w += b.w;
    return a;
}

// grid barrier: per-thread RELEASE fence before arrival; no acquire fence
// (all mutable cross-CTA data is read via __ldcg -> L2, the coherence point).
__device__ __forceinline__ void gsync(unsigned& e) {
    __threadfence();   // release: drain this thread's stores to L2
    __syncthreads();
    if (threadIdx.x == 0) {
        if (atomicAdd(&g_cnt, 1u) == GRID - 1) {
            g_cnt = 0;
            __threadfence();
            g_epoch = e + 1;
        } else {
            while (g_epoch == e) { }
        }
    }
    __syncthreads();
    e++;
}

// ---------------- the persistent kernel ----------------
__global__ void __launch_bounds__(NTHR, 1)
aligner_persistent(const float* __restrict__ enc,
                   const float* __restrict__ queries,
                   const float* __restrict__ outputs,
                   const float* __restrict__ mask,
                   const float* __restrict__ w_ih,
                   const float* __restrict__ w_hh,
                   const float* __restrict__ b_ih,
                   const float* __restrict__ b_hh,
                   const float* __restrict__ w_q,
                   const float* __restrict__ w_loc1,
                   const float* __restrict__ w_loc2,
                   const float* __restrict__ w_k,
                   const float* __restrict__ b_k,
                   const float* __restrict__ w_agg,
                   const float* __restrict__ w_t1,
                   const float* __restrict__ b_t1,
                   const float* __restrict__ w_t2,
                   float* __restrict__ out) {
    __shared__ __align__(16) float sm[8448];  // 33 KB, phase-aliased
    const int cta = blockIdx.x;
    const int tid = threadIdx.x;
    unsigned ep = g_epoch;

    // ================= phase 0: init + wcomb + key =================
    {
        int c0 = cta * 4;
        for (int idx = tid; idx < 4 * Kz; idx += NTHR) {
            int c = c0 + idx / Kz, k = idx % Kz;
            float a = 0.f;
            for (int l = 0; l < LOCz; l++)
                a += w_loc2[c * LOCz + l] * w_loc1[l * Kz + k];
            g_wcomb[c][k] = a;
        }
        for (int idx = cta * NTHR + tid; idx < Cz * Bz; idx += GRID * NTHR) {
            ((float*)g_hT)[idx] = 0.f;
            ((float*)g_hB)[idx] = 0.f;
        }
        for (int idx = cta * NTHR + tid; idx < Bz * Sz; idx += GRID * NTHR) {
            int b = idx / Sz, s = idx % Sz;
            g_alpha[b][s]   = (s == 0) ? 1.f : 0.f;
            g_align_s[b][s] = 1.f / (float)Sz;
        }
        for (int idx = cta * NTHR + tid; idx < Iz * Bz; idx += GRID * NTHR) {
            int i = idx / Bz, b = idx % Bz;
            g_prevT[i][b] = enc[((size_t)b * Sz) * Iz + i];  // alpha0 one-hot @ s=0
        }
        for (int idx = cta * NTHR + tid; idx < 32 * Bz; idx += GRID * NTHR)
            ((float*)g_zpart)[idx] = 0.f;  // sigmoid(0)=0.5 = trans0

        // key projection: CTA = (b, s-quarter), 4 tiles of 16 s
        int b = cta >> 2, sq = cta & 3;
        float* esm = sm;  // 16 x 512
        for (int tile = 0; tile < 4; tile++) {
            int s0 = sq * 64 + tile * 16;
            __syncthreads();
            const float* epp = enc + ((size_t)b * Sz + s0) * Iz;
            for (int i = tid; i < 16 * Iz; i += NTHR) esm[i] = epp[i];
            __syncthreads();
            int c = tid;  // 512 threads <-> 512 channels
            const float4* wr = (const float4*)(w_k + (size_t)c * Iz);
            const float4* ef = (const float4*)esm;
            float acc[16];
#pragma unroll
            for (int s = 0; s < 16; s++) acc[s] = 0.f;
            for (int k4 = 0; k4 < Iz / 4; k4++) {
                float4 w = wr[k4];
#pragma unroll
                for (int s = 0; s < 16; s++)
                    acc[s] += dot4(w, ef[s * (Iz / 4) + k4]);
            }
            float bk = b_k[c];
#pragma unroll
            for (int s = 0; s < 16; s++) g_key[b][s0 + s][c] = acc[s] + bk;
        }
    }
    gsync(ep);

    // ================= time loop =================
    for (int t = 0; t < Tz; t++) {
        const int cur = t & 1, nxt = cur ^ 1;

        // ---------- P1: GRU rows (ctas 0..95) || TRANS(t-1) rows (ctas 96..127) ----------
        {
            const int rl = tid >> 4;        // row within cta (0..31)
            const int sub = tid & 15;
            const int bq = sub & 7;         // batch quad (0..7)
            const int kh = sub >> 3;        // k half (0..1)
            const bool isGRU = (cta < 96);
            float4* abuf4 = (float4*)sm;    // 1024 float4 = 16KB chunk buffer
            float* part  = sm + 4096;       // TRANS partials [32][32]

            int r = isGRU ? cta * 32 + rl : (cta - 96) * 32 + rl;
            const float4* w0 = isGRU ? (const float4*)(w_ih + (size_t)r * XWz)
                                     : (const float4*)(w_t1 + (size_t)r * TINz);
            const float4* whp = isGRU ? (const float4*)(w_hh + (size_t)r * Cz)
                                      : w0 + (Iz + Mz) / 4;   // hidden seg base
            float4 ax = make_float4(0.f, 0.f, 0.f, 0.f);
            float4 ah = make_float4(0.f, 0.f, 0.f, 0.f);

            // ---- direct segment (immutable inputs, L1-cached) ----
            if (isGRU) {
                const float* q0 = queries + ((size_t)(bq * 4 + 0) * Tz + t) * Hz;
                const float* q1 = queries + ((size_t)(bq * 4 + 1) * Tz + t) * Hz;
                const float* q2 = queries + ((size_t)(bq * 4 + 2) * Tz + t) * Hz;
                const float* q3 = queries + ((size_t)(bq * 4 + 3) * Tz + t) * Hz;
#pragma unroll 4
                for (int k4 = kh * 32; k4 < kh * 32 + 32; k4++) {
                    float4 w = w0[k4];
                    ax.x += dot4(w, *(const float4*)(q0 + k4 * 4));
                    ax.y += dot4(w, *(const float4*)(q1 + k4 * 4));
                    ax.z += dot4(w, *(const float4*)(q2 + k4 * 4));
                    ax.w += dot4(w, *(const float4*)(q3 + k4 * 4));
                }
            } else {
                int tt = (t > 0) ? t - 1 : 0;
                const float* f0 = outputs + ((size_t)(bq * 4 + 0) * Tz + tt) * Mz;
                const float* f1 = outputs + ((size_t)(bq * 4 + 1) * Tz + tt) * Mz;
                const float* f2 = outputs + ((size_t)(bq * 4 + 2) * Tz + tt) * Mz;
                const float* f3 = outputs + ((size_t)(bq * 4 + 3) * Tz + tt) * Mz;
                const float4* wf = w0 + Iz / 4;  // frame segment
#pragma unroll
                for (int k4 = kh * 10; k4 < kh * 10 + 10; k4++) {
                    float4 w = wf[k4];
                    ax.x += dot4(w, *(const float4*)(f0 + k4 * 4));
                    ax.y += dot4(w, *(const float4*)(f1 + k4 * 4));
                    ax.z += dot4(w, *(const float4*)(f2 + k4 * 4));
                    ax.w += dot4(w, *(const float4*)(f3 + k4 * 4));
                }
            }

            // ---- staged chunks: 0..3 = prevT (512k), 4..11 = hT[cur] (1024k) ----
            const float4* prevT4 = (const float4*)g_prevT;
            const float4* hT4    = (const float4*)g_hT[cur];
            for (int ch = 0; ch < 12; ch++) {
                const float4* src = (ch < 4) ? prevT4 + ch * 1024
                                             : hT4 + (ch - 4) * 1024;
                __syncthreads();
                abuf4[tid]       = __ldcg(src + tid);
                abuf4[tid + 512] = __ldcg(src + tid + 512);
                __syncthreads();
                const float4* wseg;
                if (isGRU) wseg = (ch < 4) ? w0 + Hz / 4 + ch * 32
                                           : whp + (ch - 4) * 32;
                else       wseg = (ch < 4) ? w0 + ch * 32
                                           : whp + (ch - 4) * 32;
                float4 acc = make_float4(0.f, 0.f, 0.f, 0.f);
#pragma unroll 4
                for (int k4 = kh * 16; k4 < kh * 16 + 16; k4++) {
                    float4 w = wseg[k4];
                    int kb = k4 * 32 + bq;
                    acc = f4fma(w.x, abuf4[kb], acc);
                    acc = f4fma(w.y, abuf4[kb + 8], acc);
                    acc = f4fma(w.z, abuf4[kb + 16], acc);
                    acc = f4fma(w.w, abuf4[kb + 24], acc);
                }
                if (isGRU && ch >= 4) ah = f4add(ah, acc);
                else                  ax = f4add(ax, acc);
            }

            // combine k-halves (partner lane differs only in kh bit)
            ax.x += __shfl_xor_sync(0xffffffffu, ax.x, 8);
            ax.y += __shfl_xor_sync(0xffffffffu, ax.y, 8);
            ax.z += __shfl_xor_sync(0xffffffffu, ax.z, 8);
            ax.w += __shfl_xor_sync(0xffffffffu, ax.w, 8);
            ah.x += __shfl_xor_sync(0xffffffffu, ah.x, 8);
            ah.y += __shfl_xor_sync(0xffffffffu, ah.y, 8);
            ah.z += __shfl_xor_sync(0xffffffffu, ah.z, 8);
            ah.w += __shfl_xor_sync(0xffffffffu, ah.w, 8);

            if (isGRU) {
                if (kh == 0) {
                    int b0 = bq * 4;
                    if (cta < 64) {  // r- and z-gate rows
                        float bb = b_ih[r] + b_hh[r];
                        g_gsum[b0 + 0][r] = ax.x + ah.x + bb;
                        g_gsum[b0 + 1][r] = ax.y + ah.y + bb;
                        g_gsum[b0 + 2][r] = ax.z + ah.z + bb;
                        g_gsum[b0 + 3][r] = ax.w + ah.w + bb;
                    } else {         // n-gate rows: keep x/h parts separate
                        int j = r - 2048;
                        float bx = b_ih[r], bh = b_hh[r];
                        g_gxn[b0 + 0][j] = ax.x + bx;
                        g_gxn[b0 + 1][j] = ax.y + bx;
                        g_gxn[b0 + 2][j] = ax.z + bx;
                        g_gxn[b0 + 3][j] = ax.w + bx;
                        g_ghn[b0 + 0][j] = ah.x + bh;
                        g_ghn[b0 + 1][j] = ah.y + bh;
                        g_ghn[b0 + 2][j] = ah.z + bh;
                        g_ghn[b0 + 3][j] = ah.w + bh;
                    }
                }
            } else if (t > 0) {
                float total0 = ax.x + ah.x, total1 = ax.y + ah.y;
                float total2 = ax.z + ah.z, total3 = ax.w + ah.w;
                if (kh == 0) {
                    float bt = b_t1[r], w2v = w_t2[r];
                    int b0 = bq * 4;
                    part[rl * 32 + b0 + 0] = ftanh(total0 + bt) * w2v;
                    part[rl * 32 + b0 + 1] = ftanh(total1 + bt) * w2v;
                    part[rl * 32 + b0 + 2] = ftanh(total2 + bt) * w2v;
                    part[rl * 32 + b0 + 3] = ftanh(total3 + bt) * w2v;
                }
                __syncthreads();
                if (tid < 32) {
                    float s = 0.f;
#pragma unroll
                    for (int r2 = 0; r2 < 32; r2++) s += part[r2 * 32 + tid];
                    g_zpart[cta - 96][tid] = s;
                }
            }
        }
        gsync(ep);

        // ---------- P2: GRU finish + q-proj + location conv + energy ----------
        {
            int b = cta >> 2, cs = cta & 3;
            float* hsm  = sm;          // 1024
            float* apad = sm + 1024;   // 291
            float* qp   = sm + 1316;   // 512
            float* q_sm = sm + 1828;   // 128
            float* epw  = sm + 1956;   // 1024

            if (tid < 256) {  // h_new = (1-z)*n + z*h
                int j = tid * 4;
                float4 sr  = __ldcg((const float4*)&g_gsum[b][j]);
                float4 szv = __ldcg((const float4*)&g_gsum[b][Cz + j]);
                float4 xn  = __ldcg((const float4*)&g_gxn[b][j]);
                float4 hn  = __ldcg((const float4*)&g_ghn[b][j]);
                float4 ho  = __ldcg((const float4*)&g_hB[cur][b][j]);
                float4 hv;
                {
                    float rg = fsig(sr.x), zg = fsig(szv.x);
                    hv.x = (1.f - zg) * ftanh(xn.x + rg * hn.x) + zg * ho.x;
                }
                {
                    float rg = fsig(sr.y), zg = fsig(szv.y);
                    hv.y = (1.f - zg) * ftanh(xn.y + rg * hn.y) + zg * ho.y;
                }
                {
                    float rg = fsig(sr.z), zg = fsig(szv.z);
                    hv.z = (1.f - zg) * ftanh(xn.z + rg * hn.z) + zg * ho.z;
                }
                {
                    float rg = fsig(sr.w), zg = fsig(szv.w);
                    hv.w = (1.f - zg) * ftanh(xn.w + rg * hn.w) + zg * ho.w;
                }
                *(float4*)&hsm[j] = hv;
                if (cs == 0) *(float4*)&g_hB[nxt][b][j] = hv;
            }
            for (int i = tid; i < Sz + 35; i += NTHR) {
                int s = i - 15;
                apad[i] = (s >= 0 && s < Sz) ? __ldcg(&g_align_s[b][s]) : 0.f;
            }
            __syncthreads();
            if (tid < 256) {  // transposed h_new write, j-range by slab
                int j = cs * 256 + tid;
                g_hT[nxt][j][b] = hsm[j];
            }
            {   // q[c] = w_q[c,:] . h_new   (4 threads per c)
                int cl = tid >> 2, quarter = tid & 3;
                int c = cs * 128 + cl;
                const float4* wq = (const float4*)(w_q + (size_t)c * Cz + quarter * 256);
                const float4* hv = (const float4*)(hsm + quarter * 256);
                float a = 0.f;
#pragma unroll 4
                for (int k = 0; k < 64; k++) a += dot4(wq[k], hv[k]);
                qp[tid] = a;
            }
            __syncthreads();
            if (tid < 128)
                q_sm[tid] = qp[4 * tid] + qp[4 * tid + 1] + qp[4 * tid + 2] + qp[4 * tid + 3];
            __syncthreads();

            int w = tid >> 5, lane = tid & 31;
            int cg = w & 3, sh = w >> 2;           // 4 c-groups x 4 s-groups
            int cl = cg * 32 + lane;
            int c = cs * 128 + cl;
            float wc[Kz];
#pragma unroll
            for (int k = 0; k < Kz; k++) wc[k] = g_wcomb[c][k];
            float wa = w_agg[c];
            float qc = q_sm[cl];
            int s0 = sh * 64;
            for (int sb = 0; sb < 16; sb++) {
                int s = s0 + sb * 4;
                float a0 = qc + g_key[b][s][c];
                float a1 = qc + g_key[b][s + 1][c];
                float a2 = qc + g_key[b][s + 2][c];
                float a3 = qc + g_key[b][s + 3][c];
                float x0 = apad[s], x1 = apad[s + 1], x2 = apad[s + 2], x3 = apad[s + 3];
#pragma unroll
                for (int k = 0; k < Kz; k++) {
                    float wk = wc[k];
                    a0 = fmaf(wk, x0, a0);
                    a1 = fmaf(wk, x1, a1);
                    a2 = fmaf(wk, x2, a2);
                    a3 = fmaf(wk, x3, a3);
                    x0 = x1; x1 = x2; x2 = x3; x3 = apad[s + k + 4];
                }
                float e0 = ftanh(a0) * wa;
                float e1 = ftanh(a1) * wa;
                float e2 = ftanh(a2) * wa;
                float e3 = ftanh(a3) * wa;
#pragma unroll
                for (int off = 16; off; off >>= 1) {
                    e0 += __shfl_xor_sync(0xffffffffu, e0, off);
                    e1 += __shfl_xor_sync(0xffffffffu, e1, off);
                    e2 += __shfl_xor_sync(0xffffffffu, e2, off);
                    e3 += __shfl_xor_sync(0xffffffffu, e3, off);
                }
                if (lane == 0) {  // unique (cg, s) writer
                    epw[cg * 256 + s]     = e0;
                    epw[cg * 256 + s + 1] = e1;
                    epw[cg * 256 + s + 2] = e2;
                    epw[cg * 256 + s + 3] = e3;
                }
            }
            __syncthreads();
            if (tid < 256)
                g_ep[cs][b][tid] = epw[tid] + epw[256 + tid] + epw[512 + tid] + epw[768 + tid];
        }
        gsync(ep);

        // ---------- P3: softmax + alpha update + attend (ctas 0..31) ----------
        if (cta < Bz) {
            int b = cta, s = tid;
            float* red   = sm;          // 256
            float* alnew = sm + 256;    // 256
            float* aold  = sm + 512;    // 257
            float* attb  = sm + 784;    // 4 slabs x 512 floats
            float* trsp  = sm + 2836;   // 1

            if (tid < 32) {
                float zp = __ldcg(&g_zpart[tid][b]);
#pragma unroll
                for (int off = 16; off; off >>= 1)
                    zp += __shfl_xor_sync(0xffffffffu, zp, off);
                if (tid == 0) trsp[0] = fsig(zp);
            }
            float e = 0.f;
            if (tid < 256) {
                aold[tid + 1] = g_alpha[b][tid];
                if (tid == 0) aold[0] = 0.f;
                e = __ldcg(&g_ep[0][b][s]) + __ldcg(&g_ep[1][b][s]) +
                    __ldcg(&g_ep[2][b][s]) + __ldcg(&g_ep[3][b][s]);
                if (mask[b * Sz + s] == 0.f) e = -1e30f;
                red[tid] = e;
            }
            __syncthreads();
            for (int o = 128; o; o >>= 1) {
                if (tid < o) red[tid] = fmaxf(red[tid], red[tid + o]);
                __syncthreads();
            }
            float m = red[0]; __syncthreads();
            float ex = 0.f;
            if (tid < 256) { ex = __expf(e - m); red[tid] = ex; }
            __syncthreads();
            for (int o = 128; o; o >>= 1) {
                if (tid < o) red[tid] += red[tid + o];
                __syncthreads();
            }
            float aln = __fdividef(ex, red[0]);
            float tr = trsp[0];
            float raw = 0.f;
            if (tid < 256)
                raw = ((1.f - tr) * aold[s + 1] + tr * aold[s] + 1e-7f) * aln;
            __syncthreads();
            if (tid < 256) red[tid] = raw;
            __syncthreads();
            for (int o = 128; o; o >>= 1) {
                if (tid < o) red[tid] += red[tid + o];
                __syncthreads();
            }
            if (tid < 256) {
                float an = __fdividef(raw, red[0]);
                g_alpha[b][s]   = an;
                g_align_s[b][s] = aln;
                out[((size_t)b * Tz + t) * Sz + s] = an;
                alnew[s] = an;
            }
            __syncthreads();

            // attend = enc^T alpha_new -> g_prevT (prev for step t+1)
            int i4 = tid & 127, shh = tid >> 7;   // 4 s-chunks of 64
            const float4* eb = (const float4*)(enc + (size_t)b * Sz * Iz);
            float4 acc = make_float4(0.f, 0.f, 0.f, 0.f);
            for (int s2 = shh * 64; s2 < shh * 64 + 64; s2++) {
                float a = alnew[s2];
                float4 ev = eb[(size_t)s2 * (Iz / 4) + i4];
                acc.x = fmaf(a, ev.x, acc.x);
                acc.y = fmaf(a, ev.y, acc.y);
                acc.z = fmaf(a, ev.z, acc.z);
                acc.w = fmaf(a, ev.w, acc.w);
            }
            *(float4*)&attb[(shh * 128 + i4) * 4] = acc;
            __syncthreads();
            if (tid < 128) {
                float4 o0 = *(const float4*)&attb[tid * 4];
                float4 o1 = *(const float4*)&attb[(128 + tid) * 4];
                float4 o2 = *(const float4*)&attb[(256 + tid) * 4];
                float4 o3 = *(const float4*)&attb[(384 + tid) * 4];
                int i = tid * 4;
                g_prevT[i][b]     = o0.x + o1.x + o2.x + o3.x;
                g_prevT[i + 1][b] = o0.y + o1.y + o2.y + o3.y;
                g_prevT[i + 2][b] = o0.z + o1.z + o2.z + o3.z;
                g_prevT[i + 3][b] = o0.w + o1.w + o2.w + o3.w;
            }
        }
        gsync(ep);
    }
}

// ---------------- driver: ONE graph node ----------------
extern "C" void kernel_launch(void* const* d_in, const int* in_sizes, int n_in,
                              void* d_out, int out_size) {
    (void)in_sizes; (void)n_in; (void)out_size;
    const float* enc     = (const float*)d_in[0];
    const float* queries = (const float*)d_in[1];
    const float* outputs = (const float*)d_in[2];
    const float* mask    = (const float*)d_in[3];
    const float* w_ih    = (const float*)d_in[4];
    const float* w_hh    = (const float*)d_in[5];
    const float* b_ih    = (const float*)d_in[6];
    const float* b_hh    = (const float*)d_in[7];
    const float* w_q     = (const float*)d_in[8];
    const float* w_loc1  = (const float*)d_in[9];
    const float* w_loc2  = (const float*)d_in[10];
    const float* w_k     = (const float*)d_in[11];
    const float* b_k     = (const float*)d_in[12];
    const float* w_agg   = (const float*)d_in[13];
    const float* w_t1    = (const float*)d_in[14];
    const float* b_t1    = (const float*)d_in[15];
    const float* w_t2    = (const float*)d_in[16];
    float* out = (float*)d_out;

    aligner_persistent<<<GRID, NTHR>>>(enc, queries, outputs, mask,
                                       w_ih, w_hh, b_ih, b_hh, w_q,
                                       w_loc1, w_loc2, w_k, b_k, w_agg,
                                       w_t1, b_t1, w_t2, out);
}

// round 15
// speedup vs baseline: 1.5055x; 1.5055x over previous
#include <cuda_runtime.h>
#include <cstdio>

#define Bz 32
#define Sz 256
#define Iz 512
#define Hz 256
#define Mz 80
#define Cz 1024
#define C2z 512
#define LOCz 32
#define Kz 31
#define Tz 800
#define XWz (Hz + Iz)         /* 768  */
#define TINz (Iz + Mz + Cz)   /* 1616 */
#define GRID 128
#define NTHR 512

// ---------------- persistent device scratch ----------------
__device__ __align__(16) float g_key[Bz][Sz][C2z];   // immutable after P0
__device__ __align__(16) float g_qT[Tz * Hz * Bz];   // queries transposed [t][k][b]
__device__ __align__(16) float g_fT[Tz * Mz * Bz];   // frames transposed [t][k][b]
__device__ __align__(16) float g_hT[2][Cz][Bz];      // mutable: P2 -> P1
__device__ __align__(16) float g_hB[2][Bz][Cz];      // mutable: P2 -> P2
__device__ __align__(16) float g_prevT[Iz][Bz];      // mutable: P3 -> P1
__device__ __align__(16) float g_alpha[Bz][Sz];      // same-CTA only (P3)
__device__ __align__(16) float g_align_s[Bz][Sz];    // mutable: P3 -> P2
__device__ __align__(16) float g_gsum[Bz][2 * Cz];   // mutable: P1 -> P2
__device__ __align__(16) float g_gxn[Bz][Cz];        // mutable: P1 -> P2
__device__ __align__(16) float g_ghn[Bz][Cz];        // mutable: P1 -> P2
__device__ __align__(16) float g_wcomb[C2z][Kz];     // immutable after P0
__device__ __align__(16) float g_ep[4][Bz][Sz];      // mutable: P2 -> P3
__device__ __align__(16) float g_zpart[32][Bz];      // mutable: P1 -> P3
__device__ unsigned g_cnt;
__device__ volatile unsigned g_epoch;

// ---------------- helpers ----------------
__device__ __forceinline__ float fsig(float x) {
    return __fdividef(1.f, 1.f + __expf(-x));
}
__device__ __forceinline__ float ftanh(float x) {
    float ax = fabsf(x);
    float e  = __expf(-2.f * ax);
    float r  = __fdividef(1.f - e, 1.f + e);
    return copysignf(r, x);
}
__device__ __forceinline__ float dot4(float4 a, float4 b) {
    return a.x * b.x + a.y * b.y + a.z * b.z + a.w * b.w;
}
__device__ __forceinline__ int swz(int v) { return v ^ ((v >> 6) & 7); }

// grid barrier: per-thread release fence; readers of mutable data use __ldcg.
__device__ __forceinline__ void gsync(unsigned& e) {
    __threadfence();
    __syncthreads();
    if (threadIdx.x == 0) {
        if (atomicAdd(&g_cnt, 1u) == GRID - 1) {
            g_cnt = 0;
            __threadfence();
            g_epoch = e + 1;
        } else {
            while (g_epoch == e) { }
        }
    }
    __syncthreads();
    e++;
}

#define FMA8(rr, cw)                                        \
    acc[rr][0] = fmaf(cw, a0.x, acc[rr][0]);                \
    acc[rr][1] = fmaf(cw, a0.y, acc[rr][1]);                \
    acc[rr][2] = fmaf(cw, a0.z, acc[rr][2]);                \
    acc[rr][3] = fmaf(cw, a0.w, acc[rr][3]);                \
    acc[rr][4] = fmaf(cw, a1.x, acc[rr][4]);                \
    acc[rr][5] = fmaf(cw, a1.y, acc[rr][5]);                \
    acc[rr][6] = fmaf(cw, a1.z, acc[rr][6]);                \
    acc[rr][7] = fmaf(cw, a1.w, acc[rr][7]);

// one 128-k chunk: 4 rows x 8 batches x 8 k per thread (k-slice ks)
__device__ __forceinline__ void chunk_mma(
    float acc[4][8],
    const float4* w0p, const float4* w1p,
    const float4* w2p, const float4* w3p,
    int wk0, const float4* abuf4, int ks, int bo) {
#pragma unroll
    for (int j = 0; j < 2; j++) {
        int k4 = wk0 + ks * 2 + j;
        float4 w0 = w0p[k4], w1 = w1p[k4], w2 = w2p[k4], w3 = w3p[k4];
        float c0[4] = {w0.x, w0.y, w0.z, w0.w};
        float c1[4] = {w1.x, w1.y, w1.z, w1.w};
        float c2[4] = {w2.x, w2.y, w2.z, w2.w};
        float c3[4] = {w3.x, w3.y, w3.z, w3.w};
#pragma unroll
        for (int kk = 0; kk < 4; kk++) {
            int k = (ks * 2 + j) * 4 + kk;
            int v0 = k * 8 + bo * 2;
            float4 a0 = abuf4[swz(v0)];
            float4 a1 = abuf4[swz(v0 + 1)];
            FMA8(0, c0[kk]) FMA8(1, c1[kk]) FMA8(2, c2[kk]) FMA8(3, c3[kk])
        }
    }
}

__device__ __forceinline__ void reduce32(float acc[4][8]) {
#pragma unroll
    for (int off = 1; off <= 8; off <<= 1)
#pragma unroll
        for (int rr = 0; rr < 4; rr++)
#pragma unroll
            for (int bb = 0; bb < 8; bb++)
                acc[rr][bb] += __shfl_xor_sync(0xffffffffu, acc[rr][bb], off);
}

// ---------------- the persistent kernel ----------------
__global__ void __launch_bounds__(NTHR, 1)
aligner_persistent(const float* __restrict__ enc,
                   const float* __restrict__ queries,
                   const float* __restrict__ outputs,
                   const float* __restrict__ mask,
                   const float* __restrict__ w_ih,
                   const float* __restrict__ w_hh,
                   const float* __restrict__ b_ih,
                   const float* __restrict__ b_hh,
                   const float* __restrict__ w_q,
                   const float* __restrict__ w_loc1,
                   const float* __restrict__ w_loc2,
                   const float* __restrict__ w_k,
                   const float* __restrict__ b_k,
                   const float* __restrict__ w_agg,
                   const float* __restrict__ w_t1,
                   const float* __restrict__ b_t1,
                   const float* __restrict__ w_t2,
                   float* __restrict__ out) {
    __shared__ __align__(16) float sm[8448];  // 33 KB, phase-aliased
    unsigned* tmr = (unsigned*)(sm + 8440);   // 6 phase timers (diagnostic)
    const int cta = blockIdx.x;
    const int tid = threadIdx.x;
    unsigned ep = g_epoch;
    if (tid == 0)
        for (int i = 0; i < 6; i++) tmr[i] = 0;

    // ================= phase 0: init + wcomb + transposes + key =================
    {
        int c0 = cta * 4;
        for (int idx = tid; idx < 4 * Kz; idx += NTHR) {
            int c = c0 + idx / Kz, k = idx % Kz;
            float a = 0.f;
            for (int l = 0; l < LOCz; l++)
                a += w_loc2[c * LOCz + l] * w_loc1[l * Kz + k];
            g_wcomb[c][k] = a;
        }
        for (int idx = cta * NTHR + tid; idx < Cz * Bz; idx += GRID * NTHR) {
            ((float*)g_hT)[idx] = 0.f;
            ((float*)g_hB)[idx] = 0.f;
        }
        for (int idx = cta * NTHR + tid; idx < Bz * Sz; idx += GRID * NTHR) {
            int b = idx / Sz, s = idx % Sz;
            g_alpha[b][s]   = (s == 0) ? 1.f : 0.f;
            g_align_s[b][s] = 1.f / (float)Sz;
        }
        for (int idx = cta * NTHR + tid; idx < Iz * Bz; idx += GRID * NTHR) {
            int i = idx / Bz, b = idx % Bz;
            g_prevT[i][b] = enc[((size_t)b * Sz) * Iz + i];
        }
        for (int idx = cta * NTHR + tid; idx < 32 * Bz; idx += GRID * NTHR)
            ((float*)g_zpart)[idx] = 0.f;
        // transpose queries -> [t][k][b]
        for (int idx = cta * NTHR + tid; idx < Tz * Hz * Bz; idx += GRID * NTHR) {
            int b = idx & 31;
            int k = (idx >> 5) & (Hz - 1);
            int tq = idx >> 13;
            g_qT[idx] = queries[((size_t)b * Tz + tq) * Hz + k];
        }
        // transpose frames -> [t][k][b]
        for (int idx = cta * NTHR + tid; idx < Tz * Mz * Bz; idx += GRID * NTHR) {
            int b = idx & 31;
            int r2 = idx >> 5;
            int k = r2 % Mz;
            int tq = r2 / Mz;
            g_fT[idx] = outputs[((size_t)b * Tz + tq) * Mz + k];
        }

        // key projection: CTA = (b, s-quarter), 4 tiles of 16 s
        int b = cta >> 2, sq = cta & 3;
        float* esm = sm;  // 16 x 512
        for (int tile = 0; tile < 4; tile++) {
            int s0 = sq * 64 + tile * 16;
            __syncthreads();
            const float* epp = enc + ((size_t)b * Sz + s0) * Iz;
            for (int i = tid; i < 16 * Iz; i += NTHR) esm[i] = epp[i];
            __syncthreads();
            int c = tid;
            const float4* wr = (const float4*)(w_k + (size_t)c * Iz);
            const float4* ef = (const float4*)esm;
            float acc[16];
#pragma unroll
            for (int s = 0; s < 16; s++) acc[s] = 0.f;
            for (int k4 = 0; k4 < Iz / 4; k4++) {
                float4 w = wr[k4];
#pragma unroll
                for (int s = 0; s < 16; s++)
                    acc[s] += dot4(w, ef[s * (Iz / 4) + k4]);
            }
            float bk = b_k[c];
#pragma unroll
            for (int s = 0; s < 16; s++) g_key[b][s0 + s][c] = acc[s] + bk;
        }
    }
    gsync(ep);

    // ================= time loop =================
    for (int t = 0; t < Tz; t++) {
        const int cur = t & 1, nxt = cur ^ 1;
        unsigned s0 = clock();

        // ---------- P1: register-tiled GEMMs ----------
        {
            const int ks = tid & 15, bo = (tid >> 4) & 3, rq = tid >> 6;
            float4* abuf4 = (float4*)sm;       // 16 KB staged activations
            float* part = sm + 4096;           // TRANS partials [32][32]
            const float4* prevT4 = (const float4*)g_prevT;
            const float4* hT4    = (const float4*)g_hT[cur];

            if (cta < 96) {  // GRU rows
                const int r0 = cta * 32 + rq * 4;
                const bool ngate = (cta >= 64);
                const float4* wx0 = (const float4*)(w_ih + (size_t)(r0 + 0) * XWz);
                const float4* wx1 = (const float4*)(w_ih + (size_t)(r0 + 1) * XWz);
                const float4* wx2 = (const float4*)(w_ih + (size_t)(r0 + 2) * XWz);
                const float4* wx3 = (const float4*)(w_ih + (size_t)(r0 + 3) * XWz);
                const float4* wh0 = (const float4*)(w_hh + (size_t)(r0 + 0) * Cz);
                const float4* wh1 = (const float4*)(w_hh + (size_t)(r0 + 1) * Cz);
                const float4* wh2 = (const float4*)(w_hh + (size_t)(r0 + 2) * Cz);
                const float4* wh3 = (const float4*)(w_hh + (size_t)(r0 + 3) * Cz);
                const float4* qT4 = (const float4*)(g_qT + (size_t)t * (Hz * Bz));
                float accA[4][8], accB[4][8];
#pragma unroll
                for (int rr = 0; rr < 4; rr++)
#pragma unroll
                    for (int bb = 0; bb < 8; bb++) { accA[rr][bb] = 0.f; accB[rr][bb] = 0.f; }

                for (int c = 0; c < 14; c++) {
                    const float4* src = (c < 2) ? qT4 + c * 1024
                                     : (c < 6) ? prevT4 + (c - 2) * 1024
                                               : hT4 + (c - 6) * 1024;
                    __syncthreads();
                    abuf4[swz(tid)]       = __ldcg(src + tid);
                    abuf4[swz(tid + 512)] = __ldcg(src + tid + 512);
                    __syncthreads();
                    if (c < 6)
                        chunk_mma(accA, wx0, wx1, wx2, wx3, c * 32, abuf4, ks, bo);
                    else if (!ngate)
                        chunk_mma(accA, wh0, wh1, wh2, wh3, (c - 6) * 32, abuf4, ks, bo);
                    else
                        chunk_mma(accB, wh0, wh1, wh2, wh3, (c - 6) * 32, abuf4, ks, bo);
                }
                reduce32(accA);
                if (ngate) reduce32(accB);
                if (ks == 0) {
                    if (!ngate) {
#pragma unroll
                        for (int rr = 0; rr < 4; rr++) {
                            int r = r0 + rr;
                            float bsum = b_ih[r] + b_hh[r];
#pragma unroll
                            for (int bb = 0; bb < 8; bb++)
                                g_gsum[bo * 8 + bb][r] = accA[rr][bb] + bsum;
                        }
                    } else {
#pragma unroll
                        for (int rr = 0; rr < 4; rr++) {
                            int r = r0 + rr;
                            int j = r - 2048;
                            float bx = b_ih[r], bh = b_hh[r];
#pragma unroll
                            for (int bb = 0; bb < 8; bb++) {
                                g_gxn[bo * 8 + bb][j] = accA[rr][bb] + bx;
                                g_ghn[bo * 8 + bb][j] = accB[rr][bb] + bh;
                            }
                        }
                    }
                }
            } else if (t > 0) {  // TRANS(t-1) rows
                const int r0 = (cta - 96) * 32 + rq * 4;
                const float4* wt0 = (const float4*)(w_t1 + (size_t)(r0 + 0) * TINz);
                const float4* wt1 = (const float4*)(w_t1 + (size_t)(r0 + 1) * TINz);
                const float4* wt2 = (const float4*)(w_t1 + (size_t)(r0 + 2) * TINz);
                const float4* wt3 = (const float4*)(w_t1 + (size_t)(r0 + 3) * TINz);
                const float4* fT4 = (const float4*)(g_fT + (size_t)(t - 1) * (Mz * Bz));
                float acc[4][8];
#pragma unroll
                for (int rr = 0; rr < 4; rr++)
#pragma unroll
                    for (int bb = 0; bb < 8; bb++) acc[rr][bb] = 0.f;

                for (int c = 0; c < 4; c++) {  // attend (prevT) chunks
                    __syncthreads();
                    abuf4[swz(tid)]       = __ldcg(prevT4 + c * 1024 + tid);
                    abuf4[swz(tid + 512)] = __ldcg(prevT4 + c * 1024 + tid + 512);
                    __syncthreads();
                    chunk_mma(acc, wt0, wt1, wt2, wt3, c * 32, abuf4, ks, bo);
                }
                {   // frame chunk: 80 k (640 float4)
                    __syncthreads();
                    abuf4[swz(tid)] = (tid < 512) ? __ldcg(fT4 + tid)
                                                  : make_float4(0.f, 0.f, 0.f, 0.f);
                    if (tid < 128) abuf4[swz(tid + 512)] = __ldcg(fT4 + tid + 512);
                    __syncthreads();
                    const float* f0 = w_t1 + (size_t)(r0 + 0) * TINz + Iz;
                    const float* f1 = w_t1 + (size_t)(r0 + 1) * TINz + Iz;
                    const float* f2 = w_t1 + (size_t)(r0 + 2) * TINz + Iz;
                    const float* f3 = w_t1 + (size_t)(r0 + 3) * TINz + Iz;
#pragma unroll
                    for (int kk = 0; kk < 5; kk++) {
                        int k = ks * 5 + kk;
                        float c0 = f0[k], c1 = f1[k], c2 = f2[k], c3 = f3[k];
                        int v0 = k * 8 + bo * 2;
                        float4 a0 = abuf4[swz(v0)];
                        float4 a1 = abuf4[swz(v0 + 1)];
                        FMA8(0, c0) FMA8(1, c1) FMA8(2, c2) FMA8(3, c3)
                    }
                }
                for (int c = 0; c < 8; c++) {  // hidden chunks, cols 592..1615
                    __syncthreads();
                    abuf4[swz(tid)]       = __ldcg(hT4 + c * 1024 + tid);
                    abuf4[swz(tid + 512)] = __ldcg(hT4 + c * 1024 + tid + 512);
                    __syncthreads();
                    chunk_mma(acc, wt0, wt1, wt2, wt3, 148 + c * 32, abuf4, ks, bo);
                }
                reduce32(acc);
                if (ks == 0) {
#pragma unroll
                    for (int rr = 0; rr < 4; rr++) {
                        int r = r0 + rr;
                        float bt = b_t1[r], w2v = w_t2[r];
#pragma unroll
                        for (int bb = 0; bb < 8; bb++)
                            part[(rq * 4 + rr) * 32 + bo * 8 + bb] =
                                ftanh(acc[rr][bb] + bt) * w2v;
                    }
                }
                __syncthreads();
                if (tid < 32) {
                    float s = 0.f;
#pragma unroll
                    for (int r2 = 0; r2 < 32; r2++) s += part[r2 * 32 + tid];
                    g_zpart[cta - 96][tid] = s;
                }
            }
        }
        unsigned s1 = clock();
        gsync(ep);
        unsigned s2 = clock();

        // ---------- P2: GRU finish + q-proj + location conv + energy ----------
        {
            int b = cta >> 2, cs = cta & 3;
            float* hsm  = sm;          // 1024
            float* apad = sm + 1024;   // 291
            float* qp   = sm + 1316;   // 512
            float* q_sm = sm + 1828;   // 128
            float* epw  = sm + 1956;   // 1024

            if (tid < 256) {  // h_new = (1-z)*n + z*h
                int j = tid * 4;
                float4 sr  = __ldcg((const float4*)&g_gsum[b][j]);
                float4 szv = __ldcg((const float4*)&g_gsum[b][Cz + j]);
                float4 xn  = __ldcg((const float4*)&g_gxn[b][j]);
                float4 hn  = __ldcg((const float4*)&g_ghn[b][j]);
                float4 ho  = __ldcg((const float4*)&g_hB[cur][b][j]);
                float4 hv;
                {
                    float rg = fsig(sr.x), zg = fsig(szv.x);
                    hv.x = (1.f - zg) * ftanh(xn.x + rg * hn.x) + zg * ho.x;
                }
                {
                    float rg = fsig(sr.y), zg = fsig(szv.y);
                    hv.y = (1.f - zg) * ftanh(xn.y + rg * hn.y) + zg * ho.y;
                }
                {
                    float rg = fsig(sr.z), zg = fsig(szv.z);
                    hv.z = (1.f - zg) * ftanh(xn.z + rg * hn.z) + zg * ho.z;
                }
                {
                    float rg = fsig(sr.w), zg = fsig(szv.w);
                    hv.w = (1.f - zg) * ftanh(xn.w + rg * hn.w) + zg * ho.w;
                }
                *(float4*)&hsm[j] = hv;
                if (cs == 0) *(float4*)&g_hB[nxt][b][j] = hv;
            }
            for (int i = tid; i < Sz + 35; i += NTHR) {
                int s = i - 15;
                apad[i] = (s >= 0 && s < Sz) ? __ldcg(&g_align_s[b][s]) : 0.f;
            }
            __syncthreads();
            if (tid < 256) {
                int j = cs * 256 + tid;
                g_hT[nxt][j][b] = hsm[j];
            }
            {   // q[c] = w_q[c,:] . h_new   (4 threads per c)
                int cl = tid >> 2, quarter = tid & 3;
                int c = cs * 128 + cl;
                const float4* wq = (const float4*)(w_q + (size_t)c * Cz + quarter * 256);
                const float4* hv = (const float4*)(hsm + quarter * 256);
                float a = 0.f;
#pragma unroll 4
                for (int k = 0; k < 64; k++) a += dot4(wq[k], hv[k]);
                qp[tid] = a;
            }
            __syncthreads();
            if (tid < 128)
                q_sm[tid] = qp[4 * tid] + qp[4 * tid + 1] + qp[4 * tid + 2] + qp[4 * tid + 3];
            __syncthreads();

            int w = tid >> 5, lane = tid & 31;
            int cg = w & 3, sh = w >> 2;
            int cl = cg * 32 + lane;
            int c = cs * 128 + cl;
            float wc[Kz];
#pragma unroll
            for (int k = 0; k < Kz; k++) wc[k] = g_wcomb[c][k];
            float wa = w_agg[c];
            float qc = q_sm[cl];
            int s0v = sh * 64;
            for (int sb = 0; sb < 16; sb++) {
                int s = s0v + sb * 4;
                float a0 = qc + g_key[b][s][c];
                float a1 = qc + g_key[b][s + 1][c];
                float a2 = qc + g_key[b][s + 2][c];
                float a3 = qc + g_key[b][s + 3][c];
                float x0 = apad[s], x1 = apad[s + 1], x2 = apad[s + 2], x3 = apad[s + 3];
#pragma unroll
                for (int k = 0; k < Kz; k++) {
                    float wk = wc[k];
                    a0 = fmaf(wk, x0, a0);
                    a1 = fmaf(wk, x1, a1);
                    a2 = fmaf(wk, x2, a2);
                    a3 = fmaf(wk, x3, a3);
                    x0 = x1; x1 = x2; x2 = x3; x3 = apad[s + k + 4];
                }
                float e0 = ftanh(a0) * wa;
                float e1 = ftanh(a1) * wa;
                float e2 = ftanh(a2) * wa;
                float e3 = ftanh(a3) * wa;
#pragma unroll
                for (int off = 16; off; off >>= 1) {
                    e0 += __shfl_xor_sync(0xffffffffu, e0, off);
                    e1 += __shfl_xor_sync(0xffffffffu, e1, off);
                    e2 += __shfl_xor_sync(0xffffffffu, e2, off);
                    e3 += __shfl_xor_sync(0xffffffffu, e3, off);
                }
                if (lane == 0) {
                    epw[cg * 256 + s]     = e0;
                    epw[cg * 256 + s + 1] = e1;
                    epw[cg * 256 + s + 2] = e2;
                    epw[cg * 256 + s + 3] = e3;
                }
            }
            __syncthreads();
            if (tid < 256)
                g_ep[cs][b][tid] = epw[tid] + epw[256 + tid] + epw[512 + tid] + epw[768 + tid];
        }
        unsigned s3 = clock();
        gsync(ep);
        unsigned s4 = clock();

        // ---------- P3: softmax + alpha update + attend (ctas 0..31) ----------
        if (cta < Bz) {
            int b = cta, s = tid;
            float* red   = sm;
            float* alnew = sm + 256;
            float* aold  = sm + 512;
            float* attb  = sm + 784;
            float* trsp  = sm + 2836;

            if (tid < 32) {
                float zp = __ldcg(&g_zpart[tid][b]);
#pragma unroll
                for (int off = 16; off; off >>= 1)
                    zp += __shfl_xor_sync(0xffffffffu, zp, off);
                if (tid == 0) trsp[0] = fsig(zp);
            }
            float e = 0.f;
            if (tid < 256) {
                aold[tid + 1] = g_alpha[b][tid];
                if (tid == 0) aold[0] = 0.f;
                e = __ldcg(&g_ep[0][b][s]) + __ldcg(&g_ep[1][b][s]) +
                    __ldcg(&g_ep[2][b][s]) + __ldcg(&g_ep[3][b][s]);
                if (mask[b * Sz + s] == 0.f) e = -1e30f;
                red[tid] = e;
            }
            __syncthreads();
            for (int o = 128; o; o >>= 1) {
                if (tid < o) red[tid] = fmaxf(red[tid], red[tid + o]);
                __syncthreads();
            }
            float m = red[0]; __syncthreads();
            float ex = 0.f;
            if (tid < 256) { ex = __expf(e - m); red[tid] = ex; }
            __syncthreads();
            for (int o = 128; o; o >>= 1) {
                if (tid < o) red[tid] += red[tid + o];
                __syncthreads();
            }
            float aln = __fdividef(ex, red[0]);
            float tr = trsp[0];
            float raw = 0.f;
            if (tid < 256)
                raw = ((1.f - tr) * aold[s + 1] + tr * aold[s] + 1e-7f) * aln;
            __syncthreads();
            if (tid < 256) red[tid] = raw;
            __syncthreads();
            for (int o = 128; o; o >>= 1) {
                if (tid < o) red[tid] += red[tid + o];
                __syncthreads();
            }
            if (tid < 256) {
                float an = __fdividef(raw, red[0]);
                g_alpha[b][s]   = an;
                g_align_s[b][s] = aln;
                out[((size_t)b * Tz + t) * Sz + s] = an;
                alnew[s] = an;
            }
            __syncthreads();

            int i4 = tid & 127, shh = tid >> 7;
            const float4* eb = (const float4*)(enc + (size_t)b * Sz * Iz);
            float4 acc = make_float4(0.f, 0.f, 0.f, 0.f);
            for (int s2 = shh * 64; s2 < shh * 64 + 64; s2++) {
                float a = alnew[s2];
                float4 ev = eb[(size_t)s2 * (Iz / 4) + i4];
                acc.x = fmaf(a, ev.x, acc.x);
                acc.y = fmaf(a, ev.y, acc.y);
                acc.z = fmaf(a, ev.z, acc.z);
                acc.w = fmaf(a, ev.w, acc.w);
            }
            *(float4*)&attb[(shh * 128 + i4) * 4] = acc;
            __syncthreads();
            if (tid < 128) {
                float4 o0 = *(const float4*)&attb[tid * 4];
                float4 o1 = *(const float4*)&attb[(128 + tid) * 4];
                float4 o2 = *(const float4*)&attb[(256 + tid) * 4];
                float4 o3 = *(const float4*)&attb[(384 + tid) * 4];
                int i = tid * 4;
                g_prevT[i][b]     = o0.x + o1.x + o2.x + o3.x;
                g_prevT[i + 1][b] = o0.y + o1.y + o2.y + o3.y;
                g_prevT[i + 2][b] = o0.z + o1.z + o2.z + o3.z;
                g_prevT[i + 3][b] = o0.w + o1.w + o2.w + o3.w;
            }
        }
        unsigned s5 = clock();
        gsync(ep);
        unsigned s6 = clock();
        if (tid == 0) {
            tmr[0] += s1 - s0;  // P1
            tmr[1] += s2 - s1;  // barrier 1
            tmr[2] += s3 - s2;  // P2
            tmr[3] += s4 - s3;  // barrier 2
            tmr[4] += s5 - s4;  // P3
            tmr[5] += s6 - s5;  // barrier 3
        }
    }

    if (tid == 0 && (cta == 0 || cta == 64 || cta == 96 || cta == 127))
        printf("[phase-cyc] cta=%d P1=%u B1=%u P2=%u B2=%u P3=%u B3=%u\n",
               cta, tmr[0], tmr[1], tmr[2], tmr[3], tmr[4], tmr[5]);
}

// ---------------- driver: ONE graph node ----------------
extern "C" void kernel_launch(void* const* d_in, const int* in_sizes, int n_in,
                              void* d_out, int out_size) {
    (void)in_sizes; (void)n_in; (void)out_size;
    const float* enc     = (const float*)d_in[0];
    const float* queries = (const float*)d_in[1];
    const float* outputs = (const float*)d_in[2];
    const float* mask    = (const float*)d_in[3];
    const float* w_ih    = (const float*)d_in[4];
    const float* w_hh    = (const float*)d_in[5];
    const float* b_ih    = (const float*)d_in[6];
    const float* b_hh    = (const float*)d_in[7];
    const float* w_q     = (const float*)d_in[8];
    const float* w_loc1  = (const float*)d_in[9];
    const float* w_loc2  = (const float*)d_in[10];
    const float* w_k     = (const float*)d_in[11];
    const float* b_k     = (const float*)d_in[12];
    const float* w_agg   = (const float*)d_in[13];
    const float* w_t1    = (const float*)d_in[14];
    const float* b_t1    = (const float*)d_in[15];
    const float* w_t2    = (const float*)d_in[16];
    float* out = (float*)d_out;

    aligner_persistent<<<GRID, NTHR>>>(enc, queries, outputs, mask,
                                       w_ih, w_hh, b_ih, b_hh, w_q,
                                       w_loc1, w_loc2, w_k, b_k, w_agg,
                                       w_t1, b_t1, w_t2, out);
}

// round 16
// speedup vs baseline: 1.5683x; 1.0418x over previous
#include <cuda_runtime.h>

#define Bz 32
#define Sz 256
#define Iz 512
#define Hz 256
#define Mz 80
#define Cz 1024
#define C2z 512
#define LOCz 32
#define Kz 31
#define Tz 800
#define XWz (Hz + Iz)         /* 768  */
#define TINz (Iz + Mz + Cz)   /* 1616 */
#define GRID 128
#define NTHR 512

typedef unsigned long long ull;

// ---------------- persistent device scratch ----------------
__device__ __align__(16) float g_key[Bz][Sz][C2z];   // immutable after P0
__device__ __align__(16) float g_qT[Tz * Hz * Bz];   // queries transposed [t][k][b]
__device__ __align__(16) float g_fT[Tz * Mz * Bz];   // frames transposed [t][k][b]
__device__ __align__(16) float g_hT[2][Cz][Bz];      // mutable: P2 -> P1
__device__ __align__(16) float g_hB[2][Bz][Cz];      // mutable: P2 -> P2
__device__ __align__(16) float g_prevT[Iz][Bz];      // mutable: P3 -> P1
__device__ __align__(16) float g_alpha[Bz][Sz];      // same-CTA only (P3)
__device__ __align__(16) float g_align_s[Bz][Sz];    // mutable: P3 -> P2
__device__ __align__(16) float g_gsum[Bz][2 * Cz];   // mutable: P1 -> P2
__device__ __align__(16) float g_gxn[Bz][Cz];        // mutable: P1 -> P2
__device__ __align__(16) float g_ghn[Bz][Cz];        // mutable: P1 -> P2
__device__ __align__(16) float g_wcomb[C2z][Kz];     // immutable after P0
__device__ __align__(16) float g_ep[4][Bz][Sz];      // mutable: P2 -> P3
__device__ __align__(16) float g_zpart[32][Bz];      // mutable: P1 -> P3
__device__ unsigned g_cnt;
__device__ volatile unsigned g_epoch;

// ---------------- helpers ----------------
__device__ __forceinline__ float fsig(float x) {
    return __fdividef(1.f, 1.f + __expf(-x));
}
__device__ __forceinline__ float ftanh(float x) {
    float ax = fabsf(x);
    float e  = __expf(-2.f * ax);
    float r  = __fdividef(1.f - e, 1.f + e);
    return copysignf(r, x);
}
__device__ __forceinline__ float dot4(float4 a, float4 b) {
    return a.x * b.x + a.y * b.y + a.z * b.z + a.w * b.w;
}
__device__ __forceinline__ int swz(int v) { return v ^ ((v >> 6) & 7); }

// packed f32x2 primitives
__device__ __forceinline__ void fma2(ull& d, ull a, ull b) {
    asm("fma.rn.f32x2 %0, %1, %2, %0;" : "+l"(d) : "l"(a), "l"(b));
}
__device__ __forceinline__ void add2(ull& d, ull o) {
    asm("add.rn.f32x2 %0, %0, %1;" : "+l"(d) : "l"(o));
}
__device__ __forceinline__ ull pk(float w) {
    ull r;
    asm("mov.b64 %0, {%1, %1};" : "=l"(r) : "f"(w));
    return r;
}
__device__ __forceinline__ float2 upk(ull v) {
    float2 f;
    asm("mov.b64 {%0, %1}, %2;" : "=f"(f.x), "=f"(f.y) : "l"(v));
    return f;
}

// grid barrier: per-thread release fence; readers of mutable data use __ldcg.
__device__ __forceinline__ void gsync(unsigned& e) {
    __threadfence();
    __syncthreads();
    if (threadIdx.x == 0) {
        if (atomicAdd(&g_cnt, 1u) == GRID - 1) {
            g_cnt = 0;
            __threadfence();
            g_epoch = e + 1;
        } else {
            while (g_epoch == e) { }
        }
    }
    __syncthreads();
    e++;
}

// one 128-k chunk: 4 rows x 8 batches (4 f32x2 pairs) x 8 k per thread
__device__ __forceinline__ void chunk_mma2(
    ull acc[4][4],
    const float4* w0p, const float4* w1p,
    const float4* w2p, const float4* w3p,
    int wk0, const float4* abuf4, int ks, int bo) {
#pragma unroll
    for (int j = 0; j < 2; j++) {
        int k4 = wk0 + ks * 2 + j;
        float4 w0 = w0p[k4], w1 = w1p[k4], w2 = w2p[k4], w3 = w3p[k4];
        float c0[4] = {w0.x, w0.y, w0.z, w0.w};
        float c1[4] = {w1.x, w1.y, w1.z, w1.w};
        float c2[4] = {w2.x, w2.y, w2.z, w2.w};
        float c3[4] = {w3.x, w3.y, w3.z, w3.w};
#pragma unroll
        for (int kk = 0; kk < 4; kk++) {
            int k = (ks * 2 + j) * 4 + kk;
            int v0 = k * 8 + bo * 2;
            ulonglong2 u0 = *(const ulonglong2*)(abuf4 + swz(v0));
            ulonglong2 u1 = *(const ulonglong2*)(abuf4 + swz(v0 + 1));
            ull p0 = pk(c0[kk]), p1 = pk(c1[kk]), p2 = pk(c2[kk]), p3 = pk(c3[kk]);
            fma2(acc[0][0], u0.x, p0); fma2(acc[0][1], u0.y, p0);
            fma2(acc[0][2], u1.x, p0); fma2(acc[0][3], u1.y, p0);
            fma2(acc[1][0], u0.x, p1); fma2(acc[1][1], u0.y, p1);
            fma2(acc[1][2], u1.x, p1); fma2(acc[1][3], u1.y, p1);
            fma2(acc[2][0], u0.x, p2); fma2(acc[2][1], u0.y, p2);
            fma2(acc[2][2], u1.x, p2); fma2(acc[2][3], u1.y, p2);
            fma2(acc[3][0], u0.x, p3); fma2(acc[3][1], u0.y, p3);
            fma2(acc[3][2], u1.x, p3); fma2(acc[3][3], u1.y, p3);
        }
    }
}

__device__ __forceinline__ void reduce16p(ull acc[4][4]) {
#pragma unroll
    for (int off = 1; off <= 8; off <<= 1)
#pragma unroll
        for (int rr = 0; rr < 4; rr++)
#pragma unroll
            for (int pp = 0; pp < 4; pp++) {
                ull o = __shfl_xor_sync(0xffffffffu, acc[rr][pp], off);
                add2(acc[rr][pp], o);
            }
}

__device__ __forceinline__ void zero16(ull acc[4][4]) {
#pragma unroll
    for (int rr = 0; rr < 4; rr++)
#pragma unroll
        for (int pp = 0; pp < 4; pp++) acc[rr][pp] = 0ull;
}

// ---------------- the persistent kernel ----------------
__global__ void __launch_bounds__(NTHR, 1)
aligner_persistent(const float* __restrict__ enc,
                   const float* __restrict__ queries,
                   const float* __restrict__ outputs,
                   const float* __restrict__ mask,
                   const float* __restrict__ w_ih,
                   const float* __restrict__ w_hh,
                   const float* __restrict__ b_ih,
                   const float* __restrict__ b_hh,
                   const float* __restrict__ w_q,
                   const float* __restrict__ w_loc1,
                   const float* __restrict__ w_loc2,
                   const float* __restrict__ w_k,
                   const float* __restrict__ b_k,
                   const float* __restrict__ w_agg,
                   const float* __restrict__ w_t1,
                   const float* __restrict__ b_t1,
                   const float* __restrict__ w_t2,
                   float* __restrict__ out) {
    __shared__ __align__(16) float sm[9216];  // 36 KB: buf0|buf1|part, phase-aliased
    const int cta = blockIdx.x;
    const int tid = threadIdx.x;
    unsigned ep = g_epoch;

    // ================= phase 0: init + wcomb + transposes + key =================
    {
        int c0 = cta * 4;
        for (int idx = tid; idx < 4 * Kz; idx += NTHR) {
            int c = c0 + idx / Kz, k = idx % Kz;
            float a = 0.f;
            for (int l = 0; l < LOCz; l++)
                a += w_loc2[c * LOCz + l] * w_loc1[l * Kz + k];
            g_wcomb[c][k] = a;
        }
        for (int idx = cta * NTHR + tid; idx < Cz * Bz; idx += GRID * NTHR) {
            ((float*)g_hT)[idx] = 0.f;
            ((float*)g_hB)[idx] = 0.f;
        }
        for (int idx = cta * NTHR + tid; idx < Bz * Sz; idx += GRID * NTHR) {
            int b = idx / Sz, s = idx % Sz;
            g_alpha[b][s]   = (s == 0) ? 1.f : 0.f;
            g_align_s[b][s] = 1.f / (float)Sz;
        }
        for (int idx = cta * NTHR + tid; idx < Iz * Bz; idx += GRID * NTHR) {
            int i = idx / Bz, b = idx % Bz;
            g_prevT[i][b] = enc[((size_t)b * Sz) * Iz + i];
        }
        for (int idx = cta * NTHR + tid; idx < 32 * Bz; idx += GRID * NTHR)
            ((float*)g_zpart)[idx] = 0.f;
        // transpose queries -> [t][k][b]
        for (int idx = cta * NTHR + tid; idx < Tz * Hz * Bz; idx += GRID * NTHR) {
            int b = idx & 31;
            int k = (idx >> 5) & (Hz - 1);
            int tq = idx >> 13;
            g_qT[idx] = queries[((size_t)b * Tz + tq) * Hz + k];
        }
        // transpose frames -> [t][k][b]
        for (int idx = cta * NTHR + tid; idx < Tz * Mz * Bz; idx += GRID * NTHR) {
            int b = idx & 31;
            int r2 = idx >> 5;
            int k = r2 % Mz;
            int tq = r2 / Mz;
            g_fT[idx] = outputs[((size_t)b * Tz + tq) * Mz + k];
        }

        // key projection: CTA = (b, s-quarter), 4 tiles of 16 s
        int b = cta >> 2, sq = cta & 3;
        float* esm = sm;  // 16 x 512
        for (int tile = 0; tile < 4; tile++) {
            int s0 = sq * 64 + tile * 16;
            __syncthreads();
            const float* epp = enc + ((size_t)b * Sz + s0) * Iz;
            for (int i = tid; i < 16 * Iz; i += NTHR) esm[i] = epp[i];
            __syncthreads();
            int c = tid;
            const float4* wr = (const float4*)(w_k + (size_t)c * Iz);
            const float4* ef = (const float4*)esm;
            float acc[16];
#pragma unroll
            for (int s = 0; s < 16; s++) acc[s] = 0.f;
            for (int k4 = 0; k4 < Iz / 4; k4++) {
                float4 w = wr[k4];
#pragma unroll
                for (int s = 0; s < 16; s++)
                    acc[s] += dot4(w, ef[s * (Iz / 4) + k4]);
            }
            float bk = b_k[c];
#pragma unroll
            for (int s = 0; s < 16; s++) g_key[b][s0 + s][c] = acc[s] + bk;
        }
    }
    gsync(ep);

    // ================= time loop =================
    for (int t = 0; t < Tz; t++) {
        const int cur = t & 1, nxt = cur ^ 1;

        // ---------- P1: double-buffered packed-f32x2 GEMMs ----------
        {
            const int ks = tid & 15, bo = (tid >> 4) & 3, rq = tid >> 6;
            float4* buf0 = (float4*)sm;            // 16 KB
            float4* buf1 = buf0 + 1024;            // 16 KB
            float* part = sm + 8192;               // TRANS partials [32][32]
            const float4* prevT4 = (const float4*)g_prevT;
            const float4* hT4    = (const float4*)g_hT[cur];

            if (cta < 96) {  // GRU rows
                const int r0 = cta * 32 + rq * 4;
                const bool ngate = (cta >= 64);
                const float4* wx0 = (const float4*)(w_ih + (size_t)(r0 + 0) * XWz);
                const float4* wx1 = (const float4*)(w_ih + (size_t)(r0 + 1) * XWz);
                const float4* wx2 = (const float4*)(w_ih + (size_t)(r0 + 2) * XWz);
                const float4* wx3 = (const float4*)(w_ih + (size_t)(r0 + 3) * XWz);
                const float4* wh0 = (const float4*)(w_hh + (size_t)(r0 + 0) * Cz);
                const float4* wh1 = (const float4*)(w_hh + (size_t)(r0 + 1) * Cz);
                const float4* wh2 = (const float4*)(w_hh + (size_t)(r0 + 2) * Cz);
                const float4* wh3 = (const float4*)(w_hh + (size_t)(r0 + 3) * Cz);
                const float4* qT4 = (const float4*)(g_qT + (size_t)t * (Hz * Bz));
                ull acc[4][4];
                zero16(acc);

                float4 p0 = __ldcg(qT4 + tid), p1 = __ldcg(qT4 + tid + 512);
                buf0[swz(tid)] = p0;
                buf0[swz(tid + 512)] = p1;
                __syncthreads();
                for (int c = 0; c < 14; c++) {
                    if (c < 13) {
                        const float4* sn = (c + 1 < 2) ? qT4 + (c + 1) * 1024
                                         : (c + 1 < 6) ? prevT4 + (c - 1) * 1024
                                                       : hT4 + (c - 5) * 1024;
                        p0 = __ldcg(sn + tid);
                        p1 = __ldcg(sn + tid + 512);
                    }
                    const float4* rb = (c & 1) ? buf1 : buf0;
                    if (c < 6) chunk_mma2(acc, wx0, wx1, wx2, wx3, c * 32, rb, ks, bo);
                    else       chunk_mma2(acc, wh0, wh1, wh2, wh3, (c - 6) * 32, rb, ks, bo);
                    if (ngate && c == 5) {  // flush x-part of n-gate
                        reduce16p(acc);
                        if (ks == 0) {
#pragma unroll
                            for (int rr = 0; rr < 4; rr++) {
                                int r = r0 + rr, jj = r - 2048;
                                float bx = b_ih[r];
#pragma unroll
                                for (int pp = 0; pp < 4; pp++) {
                                    float2 v = upk(acc[rr][pp]);
                                    g_gxn[bo * 8 + pp * 2][jj]     = v.x + bx;
                                    g_gxn[bo * 8 + pp * 2 + 1][jj] = v.y + bx;
                                }
                            }
                        }
                        zero16(acc);
                    }
                    if (c < 13) {
                        float4* wb = (c & 1) ? buf0 : buf1;
                        wb[swz(tid)] = p0;
                        wb[swz(tid + 512)] = p1;
                    }
                    __syncthreads();
                }
                reduce16p(acc);
                if (ks == 0) {
                    if (!ngate) {  // r/z rows: acc = x-part + h-part
#pragma unroll
                        for (int rr = 0; rr < 4; rr++) {
                            int r = r0 + rr;
                            float bs = b_ih[r] + b_hh[r];
#pragma unroll
                            for (int pp = 0; pp < 4; pp++) {
                                float2 v = upk(acc[rr][pp]);
                                g_gsum[bo * 8 + pp * 2][r]     = v.x + bs;
                                g_gsum[bo * 8 + pp * 2 + 1][r] = v.y + bs;
                            }
                        }
                    } else {       // n rows: acc = h-part only
#pragma unroll
                        for (int rr = 0; rr < 4; rr++) {
                            int r = r0 + rr, jj = r - 2048;
                            float bh = b_hh[r];
#pragma unroll
                            for (int pp = 0; pp < 4; pp++) {
                                float2 v = upk(acc[rr][pp]);
                                g_ghn[bo * 8 + pp * 2][jj]     = v.x + bh;
                                g_ghn[bo * 8 + pp * 2 + 1][jj] = v.y + bh;
                            }
                        }
                    }
                }
            } else if (t > 0) {  // TRANS(t-1) rows
                const int r0 = (cta - 96) * 32 + rq * 4;
                const float4* wt0 = (const float4*)(w_t1 + (size_t)(r0 + 0) * TINz);
                const float4* wt1 = (const float4*)(w_t1 + (size_t)(r0 + 1) * TINz);
                const float4* wt2 = (const float4*)(w_t1 + (size_t)(r0 + 2) * TINz);
                const float4* wt3 = (const float4*)(w_t1 + (size_t)(r0 + 3) * TINz);
                const float4* fT4 = (const float4*)(g_fT + (size_t)(t - 1) * (Mz * Bz));
                ull acc[4][4];
                zero16(acc);

                float4 p0 = __ldcg(prevT4 + tid), p1 = __ldcg(prevT4 + tid + 512);
                buf0[swz(tid)] = p0;
                buf0[swz(tid + 512)] = p1;
                __syncthreads();
                for (int c = 0; c < 12; c++) {
                    if (c < 11) {
                        const float4* sn = (c + 1 < 4) ? prevT4 + (c + 1) * 1024
                                                       : hT4 + (c - 3) * 1024;
                        p0 = __ldcg(sn + tid);
                        p1 = __ldcg(sn + tid + 512);
                    }
                    const float4* rb = (c & 1) ? buf1 : buf0;
                    int wk0 = (c < 4) ? c * 32 : 148 + (c - 4) * 32;
                    chunk_mma2(acc, wt0, wt1, wt2, wt3, wk0, rb, ks, bo);
                    if (c < 11) {
                        float4* wb = (c & 1) ? buf0 : buf1;
                        wb[swz(tid)] = p0;
                        wb[swz(tid + 512)] = p1;
                    }
                    __syncthreads();
                }
                // frame chunk (cols 512..591): stage 640 float4, packed compute
                buf0[swz(tid)] = __ldcg(fT4 + tid % 640);  // tid<640 real; others dummy
                if (tid < 128) buf0[swz(512 + tid)] = __ldcg(fT4 + 512 + tid);
                __syncthreads();
                {
                    const float* bf = (const float*)buf0;
                    const float* f0 = w_t1 + (size_t)(r0 + 0) * TINz + Iz;
                    const float* f1 = w_t1 + (size_t)(r0 + 1) * TINz + Iz;
                    const float* f2 = w_t1 + (size_t)(r0 + 2) * TINz + Iz;
                    const float* f3 = w_t1 + (size_t)(r0 + 3) * TINz + Iz;
#pragma unroll
                    for (int kk2 = 0; kk2 < 5; kk2++) {
                        int k = ks * 5 + kk2;
                        ull q0 = pk(f0[k]), q1 = pk(f1[k]), q2 = pk(f2[k]), q3 = pk(f3[k]);
                        int base0 = swz(k * 8 + bo * 2) * 4;
                        int base1 = swz(k * 8 + bo * 2 + 1) * 4;
                        ull a0 = *(const ull*)(bf + base0);
                        ull a1 = *(const ull*)(bf + base0 + 2);
                        ull a2 = *(const ull*)(bf + base1);
                        ull a3 = *(const ull*)(bf + base1 + 2);
                        fma2(acc[0][0], a0, q0); fma2(acc[0][1], a1, q0);
                        fma2(acc[0][2], a2, q0); fma2(acc[0][3], a3, q0);
                        fma2(acc[1][0], a0, q1); fma2(acc[1][1], a1, q1);
                        fma2(acc[1][2], a2, q1); fma2(acc[1][3], a3, q1);
                        fma2(acc[2][0], a0, q2); fma2(acc[2][1], a1, q2);
                        fma2(acc[2][2], a2, q2); fma2(acc[2][3], a3, q2);
                        fma2(acc[3][0], a0, q3); fma2(acc[3][1], a1, q3);
                        fma2(acc[3][2], a2, q3); fma2(acc[3][3], a3, q3);
                    }
                }
                reduce16p(acc);
                if (ks == 0) {
#pragma unroll
                    for (int rr = 0; rr < 4; rr++) {
                        int r = r0 + rr;
                        float bt = b_t1[r], w2v = w_t2[r];
#pragma unroll
                        for (int pp = 0; pp < 4; pp++) {
                            float2 v = upk(acc[rr][pp]);
                            part[(rq * 4 + rr) * 32 + bo * 8 + pp * 2]     = ftanh(v.x + bt) * w2v;
                            part[(rq * 4 + rr) * 32 + bo * 8 + pp * 2 + 1] = ftanh(v.y + bt) * w2v;
                        }
                    }
                }
                __syncthreads();
                if (tid < 32) {
                    float s = 0.f;
#pragma unroll
                    for (int r2 = 0; r2 < 32; r2++) s += part[r2 * 32 + tid];
                    g_zpart[cta - 96][tid] = s;
                }
            }
        }
        gsync(ep);

        // ---------- P2: GRU finish + q-proj + location conv + energy ----------
        {
            int b = cta >> 2, cs = cta & 3;
            float* hsm  = sm;          // 1024
            float* apad = sm + 1024;   // 291
            float* qp   = sm + 1316;   // 512
            float* q_sm = sm + 1828;   // 128
            float* epw  = sm + 1956;   // 1024

            if (tid < 256) {  // h_new = (1-z)*n + z*h
                int j = tid * 4;
                float4 sr  = __ldcg((const float4*)&g_gsum[b][j]);
                float4 szv = __ldcg((const float4*)&g_gsum[b][Cz + j]);
                float4 xn  = __ldcg((const float4*)&g_gxn[b][j]);
                float4 hn  = __ldcg((const float4*)&g_ghn[b][j]);
                float4 ho  = __ldcg((const float4*)&g_hB[cur][b][j]);
                float4 hv;
                {
                    float rg = fsig(sr.x), zg = fsig(szv.x);
                    hv.x = (1.f - zg) * ftanh(xn.x + rg * hn.x) + zg * ho.x;
                }
                {
                    float rg = fsig(sr.y), zg = fsig(szv.y);
                    hv.y = (1.f - zg) * ftanh(xn.y + rg * hn.y) + zg * ho.y;
                }
                {
                    float rg = fsig(sr.z), zg = fsig(szv.z);
                    hv.z = (1.f - zg) * ftanh(xn.z + rg * hn.z) + zg * ho.z;
                }
                {
                    float rg = fsig(sr.w), zg = fsig(szv.w);
                    hv.w = (1.f - zg) * ftanh(xn.w + rg * hn.w) + zg * ho.w;
                }
                *(float4*)&hsm[j] = hv;
                if (cs == 0) *(float4*)&g_hB[nxt][b][j] = hv;
            }
            for (int i = tid; i < Sz + 35; i += NTHR) {
                int s = i - 15;
                apad[i] = (s >= 0 && s < Sz) ? __ldcg(&g_align_s[b][s]) : 0.f;
            }
            __syncthreads();
            if (tid < 256) {
                int j = cs * 256 + tid;
                g_hT[nxt][j][b] = hsm[j];
            }
            {   // q[c] = w_q[c,:] . h_new   (4 threads per c)
                int cl = tid >> 2, quarter = tid & 3;
                int c = cs * 128 + cl;
                const float4* wq = (const float4*)(w_q + (size_t)c * Cz + quarter * 256);
                const float4* hv = (const float4*)(hsm + quarter * 256);
                float a = 0.f;
#pragma unroll 4
                for (int k = 0; k < 64; k++) a += dot4(wq[k], hv[k]);
                qp[tid] = a;
            }
            __syncthreads();
            if (tid < 128)
                q_sm[tid] = qp[4 * tid] + qp[4 * tid + 1] + qp[4 * tid + 2] + qp[4 * tid + 3];
            __syncthreads();

            int w = tid >> 5, lane = tid & 31;
            int cg = w & 3, sh = w >> 2;
            int cl = cg * 32 + lane;
            int c = cs * 128 + cl;
            float wc[Kz];
#pragma unroll
            for (int k = 0; k < Kz; k++) wc[k] = g_wcomb[c][k];
            float wa = w_agg[c];
            float qc = q_sm[cl];
            int s0v = sh * 64;
            for (int sb = 0; sb < 16; sb++) {
                int s = s0v + sb * 4;
                float a0 = qc + g_key[b][s][c];
                float a1 = qc + g_key[b][s + 1][c];
                float a2 = qc + g_key[b][s + 2][c];
                float a3 = qc + g_key[b][s + 3][c];
                float x0 = apad[s], x1 = apad[s + 1], x2 = apad[s + 2], x3 = apad[s + 3];
#pragma unroll
                for (int k = 0; k < Kz; k++) {
                    float wk = wc[k];
                    a0 = fmaf(wk, x0, a0);
                    a1 = fmaf(wk, x1, a1);
                    a2 = fmaf(wk, x2, a2);
                    a3 = fmaf(wk, x3, a3);
                    x0 = x1; x1 = x2; x2 = x3; x3 = apad[s + k + 4];
                }
                float e0 = ftanh(a0) * wa;
                float e1 = ftanh(a1) * wa;
                float e2 = ftanh(a2) * wa;
                float e3 = ftanh(a3) * wa;
#pragma unroll
                for (int off = 16; off; off >>= 1) {
                    e0 += __shfl_xor_sync(0xffffffffu, e0, off);
                    e1 += __shfl_xor_sync(0xffffffffu, e1, off);
                    e2 += __shfl_xor_sync(0xffffffffu, e2, off);
                    e3 += __shfl_xor_sync(0xffffffffu, e3, off);
                }
                if (lane == 0) {
                    epw[cg * 256 + s]     = e0;
                    epw[cg * 256 + s + 1] = e1;
                    epw[cg * 256 + s + 2] = e2;
                    epw[cg * 256 + s + 3] = e3;
                }
            }
            __syncthreads();
            if (tid < 256)
                g_ep[cs][b][tid] = epw[tid] + epw[256 + tid] + epw[512 + tid] + epw[768 + tid];
        }
        gsync(ep);

        // ---------- P3: softmax + alpha update + attend (ctas 0..31) ----------
        if (cta < Bz) {
            int b = cta, s = tid;
            float* red   = sm;
            float* alnew = sm + 256;
            float* aold  = sm + 512;
            float* attb  = sm + 784;
            float* trsp  = sm + 2836;

            if (tid < 32) {
                float zp = __ldcg(&g_zpart[tid][b]);
#pragma unroll
                for (int off = 16; off; off >>= 1)
                    zp += __shfl_xor_sync(0xffffffffu, zp, off);
                if (tid == 0) trsp[0] = fsig(zp);
            }
            float e = 0.f;
            if (tid < 256) {
                aold[tid + 1] = g_alpha[b][tid];
                if (tid == 0) aold[0] = 0.f;
                e = __ldcg(&g_ep[0][b][s]) + __ldcg(&g_ep[1][b][s]) +
                    __ldcg(&g_ep[2][b][s]) + __ldcg(&g_ep[3][b][s]);
                if (mask[b * Sz + s] == 0.f) e = -1e30f;
                red[tid] = e;
            }
            __syncthreads();
            for (int o = 128; o; o >>= 1) {
                if (tid < o) red[tid] = fmaxf(red[tid], red[tid + o]);
                __syncthreads();
            }
            float m = red[0]; __syncthreads();
            float ex = 0.f;
            if (tid < 256) { ex = __expf(e - m); red[tid] = ex; }
            __syncthreads();
            for (int o = 128; o; o >>= 1) {
                if (tid < o) red[tid] += red[tid + o];
                __syncthreads();
            }
            float aln = __fdividef(ex, red[0]);
            float tr = trsp[0];
            float raw = 0.f;
            if (tid < 256)
                raw = ((1.f - tr) * aold[s + 1] + tr * aold[s] + 1e-7f) * aln;
            __syncthreads();
            if (tid < 256) red[tid] = raw;
            __syncthreads();
            for (int o = 128; o; o >>= 1) {
                if (tid < o) red[tid] += red[tid + o];
                __syncthreads();
            }
            if (tid < 256) {
                float an = __fdividef(raw, red[0]);
                g_alpha[b][s]   = an;
                g_align_s[b][s] = aln;
                out[((size_t)b * Tz + t) * Sz + s] = an;
                alnew[s] = an;
            }
            __syncthreads();

            int i4 = tid & 127, shh = tid >> 7;
            const float4* eb = (const float4*)(enc + (size_t)b * Sz * Iz);
            float4 acc = make_float4(0.f, 0.f, 0.f, 0.f);
            for (int s2 = shh * 64; s2 < shh * 64 + 64; s2++) {
                float a = alnew[s2];
                float4 ev = eb[(size_t)s2 * (Iz / 4) + i4];
                acc.x = fmaf(a, ev.x, acc.x);
                acc.y = fmaf(a, ev.y, acc.y);
                acc.z = fmaf(a, ev.z, acc.z);
                acc.w = fmaf(a, ev.w, acc.w);
            }
            *(float4*)&attb[(shh * 128 + i4) * 4] = acc;
            __syncthreads();
            if (tid < 128) {
                float4 o0 = *(const float4*)&attb[tid * 4];
                float4 o1 = *(const float4*)&attb[(128 + tid) * 4];
                float4 o2 = *(const float4*)&attb[(256 + tid) * 4];
                float4 o3 = *(const float4*)&attb[(384 + tid) * 4];
                int i = tid * 4;
                g_prevT[i][b]     = o0.x + o1.x + o2.x + o3.x;
                g_prevT[i + 1][b] = o0.y + o1.y + o2.y + o3.y;
                g_prevT[i + 2][b] = o0.z + o1.z + o2.z + o3.z;
                g_prevT[i + 3][b] = o0.w + o1.w + o2.w + o3.w;
            }
        }
        gsync(ep);
    }
}

// ---------------- driver: ONE graph node ----------------
extern "C" void kernel_launch(void* const* d_in, const int* in_sizes, int n_in,
                              void* d_out, int out_size) {
    (void)in_sizes; (void)n_in; (void)out_size;
    const float* enc     = (const float*)d_in[0];
    const float* queries = (const float*)d_in[1];
    const float* outputs = (const float*)d_in[2];
    const float* mask    = (const float*)d_in[3];
    const float* w_ih    = (const float*)d_in[4];
    const float* w_hh    = (const float*)d_in[5];
    const float* b_ih    = (const float*)d_in[6];
    const float* b_hh    = (const float*)d_in[7];
    const float* w_q     = (const float*)d_in[8];
    const float* w_loc1  = (const float*)d_in[9];
    const float* w_loc2  = (const float*)d_in[10];
    const float* w_k     = (const float*)d_in[11];
    const float* b_k     = (const float*)d_in[12];
    const float* w_agg   = (const float*)d_in[13];
    const float* w_t1    = (const float*)d_in[14];
    const float* b_t1    = (const float*)d_in[15];
    const float* w_t2    = (const float*)d_in[16];
    float* out = (float*)d_out;

    aligner_persistent<<<GRID, NTHR>>>(enc, queries, outputs, mask,
                                       w_ih, w_hh, b_ih, b_hh, w_q,
                                       w_loc1, w_loc2, w_k, b_k, w_agg,
                                       w_t1, b_t1, w_t2, out);
}